// round 7
// baseline (speedup 1.0000x reference)
#include <cuda_runtime.h>

typedef unsigned long long ull;

// Fixed problem shape: N=100000, IN=256, OUT=64, E=1600000 (guarded by in_sizes).
#define NMAX 100000
#define IN_DIM 256
#define OUT_DIM 64

__device__ __align__(16) float g_h[(size_t)NMAX * OUT_DIM];
__device__ float g_asrc[NMAX];
__device__ float g_adst[NMAX];
__device__ float g_emax[NMAX];
__device__ float g_denom[NMAX];

// ---------- packed f32x2 helpers (Blackwell) ----------
__device__ __forceinline__ ull packdup(float v) {
    ull r; asm("mov.b64 %0, {%1, %1};" : "=l"(r) : "f"(v)); return r;
}
__device__ __forceinline__ void fma2(ull& d, ull a, ull b) {
    asm("fma.rn.f32x2 %0, %1, %2, %0;" : "+l"(d) : "l"(a), "l"(b));
}
__device__ __forceinline__ void unpack2(ull v, float& a, float& b) {
    asm("mov.b64 {%0, %1}, %2;" : "=f"(a), "=f"(b) : "l"(v));
}

// vector reduction-add to global (sm_90+), 16B per op
__device__ __forceinline__ void red_add4(float* p, float a, float b, float c, float d) {
    asm volatile("red.global.add.v4.f32 [%0], {%1, %2, %3, %4};"
                 :: "l"(p), "f"(a), "f"(b), "f"(c), "f"(d) : "memory");
}

// float atomic max via int/uint ordering trick (init must be -inf)
__device__ __forceinline__ void atomicMaxF(float* addr, float val) {
    if (val >= 0.f) atomicMax((int*)addr, __float_as_int(val));
    else            atomicMin((unsigned int*)addr, __float_as_uint(val));
}

__device__ __forceinline__ float lrelu(float v) {
    return fmaxf(v, 0.f) + 0.2f * fminf(v, 0.f);
}

__device__ __forceinline__ int clampi(int v, int hi) {   // [0, hi)
    return min(max(v, 0), hi - 1);
}

// ---------- K0: init out=0, denom=0, emax=-inf ----------
__global__ void k_init(float* __restrict__ out, int n_out, int N) {
    int i = blockIdx.x * blockDim.x + threadIdx.x;
    if (i < n_out) out[i] = 0.f;
    if (i < N) { g_denom[i] = 0.f; g_emax[i] = __int_as_float(0xff800000); }
}

// ---------- K1: h = x @ W, a_src = h@att_src, a_dst = h@att_dst ----------
// 64x64 output tile per block, 256 threads (16x16), 4x4 register tile,
// inner product via packed fma.rn.f32x2 (2 cols per op).
#define TM 64
#define TK 32
__global__ __launch_bounds__(256)
void k_gemm(const float* __restrict__ x, const float* __restrict__ W,
            const float* __restrict__ att_s, const float* __restrict__ att_d, int N) {
    __shared__ float xs[TM][TK + 1];   // [m][k], stride 33: conflict-free scalar STS + broadcast LDS
    __shared__ float ws[TK][OUT_DIM];  // [k][n], natural row-major

    const int tid = threadIdx.x;
    const int tx = tid & 15;          // col group (4 cols)
    const int ty = tid >> 4;          // row group (4 rows)
    const int row0 = blockIdx.x * TM;

    ull acc[4][2];
#pragma unroll
    for (int i = 0; i < 4; i++) { acc[i][0] = 0ull; acc[i][1] = 0ull; }

    for (int kc = 0; kc < IN_DIM; kc += TK) {
        // load x tile: 64 rows x 32 k = 512 float4
#pragma unroll
        for (int it = 0; it < 2; ++it) {
            int idx = tid + it * 256;          // 0..511
            int m   = idx >> 3;                // row in tile
            int kq  = idx & 7;                 // float4 within k-chunk
            int gr  = row0 + m;
            float4 v = make_float4(0.f, 0.f, 0.f, 0.f);
            if (gr < N) v = *(const float4*)(x + (long long)gr * IN_DIM + kc + kq * 4);
            xs[m][kq * 4 + 0] = v.x; xs[m][kq * 4 + 1] = v.y;
            xs[m][kq * 4 + 2] = v.z; xs[m][kq * 4 + 3] = v.w;
        }
        // load W tile: 32 k x 64 n = 512 float4
#pragma unroll
        for (int it = 0; it < 2; ++it) {
            int idx = tid + it * 256;
            int k   = idx >> 4;
            int nq  = idx & 15;
            *(float4*)&ws[k][nq * 4] =
                *(const float4*)(W + (long long)(kc + k) * OUT_DIM + nq * 4);
        }
        __syncthreads();

#pragma unroll
        for (int k = 0; k < TK; ++k) {
            ulonglong2 bv = *(const ulonglong2*)&ws[k][tx * 4];  // (n0,n1),(n2,n3) packed
            float a0 = xs[ty * 4 + 0][k];
            float a1 = xs[ty * 4 + 1][k];
            float a2 = xs[ty * 4 + 2][k];
            float a3 = xs[ty * 4 + 3][k];
            ull A;
            A = packdup(a0); fma2(acc[0][0], A, bv.x); fma2(acc[0][1], A, bv.y);
            A = packdup(a1); fma2(acc[1][0], A, bv.x); fma2(acc[1][1], A, bv.y);
            A = packdup(a2); fma2(acc[2][0], A, bv.x); fma2(acc[2][1], A, bv.y);
            A = packdup(a3); fma2(acc[3][0], A, bv.x); fma2(acc[3][1], A, bv.y);
        }
        __syncthreads();
    }

    // unpack 4x4 tile
    float f[4][4];
#pragma unroll
    for (int i = 0; i < 4; i++) {
        unpack2(acc[i][0], f[i][0], f[i][1]);
        unpack2(acc[i][1], f[i][2], f[i][3]);
    }

    float as[4], ad[4];
#pragma unroll
    for (int j = 0; j < 4; j++) { as[j] = att_s[tx * 4 + j]; ad[j] = att_d[tx * 4 + j]; }

#pragma unroll
    for (int i = 0; i < 4; i++) {
        int gr = row0 + ty * 4 + i;
        if (gr < N)
            *(float4*)&g_h[(long long)gr * OUT_DIM + tx * 4] =
                make_float4(f[i][0], f[i][1], f[i][2], f[i][3]);
        float ps = f[i][0] * as[0] + f[i][1] * as[1] + f[i][2] * as[2] + f[i][3] * as[3];
        float pd = f[i][0] * ad[0] + f[i][1] * ad[1] + f[i][2] * ad[2] + f[i][3] * ad[3];
#pragma unroll
        for (int o = 8; o >= 1; o >>= 1) {
            ps += __shfl_xor_sync(0xffffffffu, ps, o);
            pd += __shfl_xor_sync(0xffffffffu, pd, o);
        }
        if (tx == 0 && gr < N) { g_asrc[gr] = ps; g_adst[gr] = pd; }
    }
}

// ---------- K2: segment max over destinations (edges + self loops) ----------
// edge_index is INT32 (JAX default x64-disabled downcasts int64 -> int32).
__global__ __launch_bounds__(256)
void k_edge_max(const int* __restrict__ ei, int E, int N) {
    long long idx = (long long)blockIdx.x * blockDim.x + threadIdx.x;
    long long ET = (long long)E + N;
    if (idx >= ET) return;
    int s, d;
    if (idx < E) { s = clampi(ei[idx], N); d = clampi(ei[E + idx], N); }
    else         { s = d = (int)(idx - E); }
    float v = lrelu(g_asrc[s] + g_adst[d]);
    atomicMaxF(&g_emax[d], v);
}

// ---------- K3: w = exp(e - emax[dst]); denom[dst] += w; out[dst] += w*h[src] ----------
// 16 threads per edge; each thread covers 4 output dims via red.v4.f32.
__global__ __launch_bounds__(256)
void k_edge_scatter(const int* __restrict__ ei, int E, int N,
                    float* __restrict__ out) {
    long long gid = (long long)blockIdx.x * blockDim.x + threadIdx.x;
    long long e = gid >> 4;
    int t = (int)(gid & 15);
    long long ET = (long long)E + N;
    if (e >= ET) return;
    int s, d;
    if (e < E) { s = clampi(ei[e], N); d = clampi(ei[E + e], N); }
    else       { s = d = (int)(e - E); }
    float v = lrelu(g_asrc[s] + g_adst[d]);
    float w = __expf(v - g_emax[d]);
    if (t == 0) atomicAdd(&g_denom[d], w);
    float4 hv = *(const float4*)&g_h[(long long)s * OUT_DIM + t * 4];
    red_add4(out + (long long)d * OUT_DIM + t * 4, w * hv.x, w * hv.y, w * hv.z, w * hv.w);
}

// ---------- K4: out = (acc/denom + bias), then row-wise L2 normalize ----------
__global__ __launch_bounds__(256)
void k_finalize(float* __restrict__ out, const float* __restrict__ bias, int N) {
    int gid = blockIdx.x * blockDim.x + threadIdx.x;
    int row = gid >> 5;
    int lane = gid & 31;
    if (row >= N) return;
    float inv = 1.f / g_denom[row];
    float o0 = out[(long long)row * OUT_DIM + lane]      * inv + bias[lane];
    float o1 = out[(long long)row * OUT_DIM + 32 + lane] * inv + bias[32 + lane];
    float ss = o0 * o0 + o1 * o1;
#pragma unroll
    for (int o = 16; o >= 1; o >>= 1) ss += __shfl_xor_sync(0xffffffffu, ss, o);
    float nrm = sqrtf(ss);
    float sc = 1.f / fmaxf(nrm, 1e-12f);
    out[(long long)row * OUT_DIM + lane]      = o0 * sc;
    out[(long long)row * OUT_DIM + 32 + lane] = o1 * sc;
}

static inline int grid1(long long work, int block) {
    long long g = (work + block - 1) / block;
    return (int)(g < 1 ? 1 : g);
}

extern "C" void kernel_launch(void* const* d_in, const int* in_sizes, int n_in,
                              void* d_out, int out_size) {
    const float* x     = (const float*)d_in[0];
    const int*   ei    = (const int*)d_in[1];     // int32! (JAX x64 disabled)
    const float* W     = (const float*)d_in[2];
    const float* att_s = (const float*)d_in[3];
    const float* att_d = (const float*)d_in[4];
    const float* bias  = (const float*)d_in[5];
    float* out = (float*)d_out;

    int       N  = in_sizes[0] / IN_DIM;
    int       E  = in_sizes[1] / 2;
    long long ET = (long long)E + N;

    // K0: init
    k_init<<<grid1((long long)N * OUT_DIM, 256), 256>>>(out, N * OUT_DIM, N);
    // K1: GEMM + attention scores
    k_gemm<<<grid1(N, TM), 256>>>(x, W, att_s, att_d, N);
    // K2: segment max
    k_edge_max<<<grid1(ET, 256), 256>>>(ei, E, N);
    // K3: exp + denom + weighted scatter
    k_edge_scatter<<<grid1(ET * 16, 256), 256>>>(ei, E, N, out);
    // K4: finalize (divide, bias, L2 normalize)
    k_finalize<<<grid1((long long)N * 32, 256), 256>>>(out, bias, N);
}

// round 9
// speedup vs baseline: 1.0042x; 1.0042x over previous
#include <cuda_runtime.h>

typedef unsigned long long ull;

// Fixed problem shape: N=100000, IN=256, OUT=64, E=1600000 (guarded by in_sizes).
#define NMAX 100000
#define IN_DIM 256
#define OUT_DIM 64

__device__ __align__(16) float g_h[(size_t)NMAX * OUT_DIM];
__device__ float g_asrc[NMAX];
__device__ float g_adst[NMAX];
__device__ float g_emax[NMAX];
__device__ float g_denom[NMAX];

// ---------- packed f32x2 helpers (Blackwell) ----------
__device__ __forceinline__ ull packdup(float v) {
    ull r; asm("mov.b64 %0, {%1, %1};" : "=l"(r) : "f"(v)); return r;
}
__device__ __forceinline__ void fma2(ull& d, ull a, ull b) {
    asm("fma.rn.f32x2 %0, %1, %2, %0;" : "+l"(d) : "l"(a), "l"(b));
}
__device__ __forceinline__ void unpack2(ull v, float& a, float& b) {
    asm("mov.b64 {%0, %1}, %2;" : "=f"(a), "=f"(b) : "l"(v));
}

// vector reduction-add to global (sm_90+), 16B per op
__device__ __forceinline__ void red_add4(float* p, float a, float b, float c, float d) {
    asm volatile("red.global.add.v4.f32 [%0], {%1, %2, %3, %4};"
                 :: "l"(p), "f"(a), "f"(b), "f"(c), "f"(d) : "memory");
}

// float atomic max via int/uint ordering trick (init must be -inf)
__device__ __forceinline__ void atomicMaxF(float* addr, float val) {
    if (val >= 0.f) atomicMax((int*)addr, __float_as_int(val));
    else            atomicMin((unsigned int*)addr, __float_as_uint(val));
}

__device__ __forceinline__ float lrelu(float v) {
    return fmaxf(v, 0.f) + 0.2f * fminf(v, 0.f);
}

__device__ __forceinline__ int clampi(int v, int hi) {   // [0, hi)
    return min(max(v, 0), hi - 1);
}

// ---------- K0: init out=0, denom=0, emax=-inf ----------
__global__ void k_init(float* __restrict__ out, int n_out, int N) {
    int i = blockIdx.x * blockDim.x + threadIdx.x;
    if (i < n_out) out[i] = 0.f;
    if (i < N) { g_denom[i] = 0.f; g_emax[i] = __int_as_float(0xff800000); }
}

// ---------- K1: h = x @ W, a_src = h@att_src, a_dst = h@att_dst ----------
// 64x64 output tile per block, 256 threads (16x16), 4x4 register tile,
// inner product via packed fma.rn.f32x2 (2 cols per op).
#define TM 64
#define TK 32
__global__ __launch_bounds__(256)
void k_gemm(const float* __restrict__ x, const float* __restrict__ W,
            const float* __restrict__ att_s, const float* __restrict__ att_d, int N) {
    __shared__ float xs[TM][TK + 1];   // [m][k], stride 33: conflict-free scalar STS + broadcast LDS
    __shared__ float ws[TK][OUT_DIM];  // [k][n], natural row-major

    const int tid = threadIdx.x;
    const int tx = tid & 15;          // col group (4 cols)
    const int ty = tid >> 4;          // row group (4 rows)
    const int row0 = blockIdx.x * TM;

    ull acc[4][2];
#pragma unroll
    for (int i = 0; i < 4; i++) { acc[i][0] = 0ull; acc[i][1] = 0ull; }

    for (int kc = 0; kc < IN_DIM; kc += TK) {
        // load x tile: 64 rows x 32 k = 512 float4
#pragma unroll
        for (int it = 0; it < 2; ++it) {
            int idx = tid + it * 256;          // 0..511
            int m   = idx >> 3;                // row in tile
            int kq  = idx & 7;                 // float4 within k-chunk
            int gr  = row0 + m;
            float4 v = make_float4(0.f, 0.f, 0.f, 0.f);
            if (gr < N) v = *(const float4*)(x + (long long)gr * IN_DIM + kc + kq * 4);
            xs[m][kq * 4 + 0] = v.x; xs[m][kq * 4 + 1] = v.y;
            xs[m][kq * 4 + 2] = v.z; xs[m][kq * 4 + 3] = v.w;
        }
        // load W tile: 32 k x 64 n = 512 float4
#pragma unroll
        for (int it = 0; it < 2; ++it) {
            int idx = tid + it * 256;
            int k   = idx >> 4;
            int nq  = idx & 15;
            *(float4*)&ws[k][nq * 4] =
                *(const float4*)(W + (long long)(kc + k) * OUT_DIM + nq * 4);
        }
        __syncthreads();

#pragma unroll
        for (int k = 0; k < TK; ++k) {
            ulonglong2 bv = *(const ulonglong2*)&ws[k][tx * 4];  // (n0,n1),(n2,n3) packed
            float a0 = xs[ty * 4 + 0][k];
            float a1 = xs[ty * 4 + 1][k];
            float a2 = xs[ty * 4 + 2][k];
            float a3 = xs[ty * 4 + 3][k];
            ull A;
            A = packdup(a0); fma2(acc[0][0], A, bv.x); fma2(acc[0][1], A, bv.y);
            A = packdup(a1); fma2(acc[1][0], A, bv.x); fma2(acc[1][1], A, bv.y);
            A = packdup(a2); fma2(acc[2][0], A, bv.x); fma2(acc[2][1], A, bv.y);
            A = packdup(a3); fma2(acc[3][0], A, bv.x); fma2(acc[3][1], A, bv.y);
        }
        __syncthreads();
    }

    // unpack 4x4 tile
    float f[4][4];
#pragma unroll
    for (int i = 0; i < 4; i++) {
        unpack2(acc[i][0], f[i][0], f[i][1]);
        unpack2(acc[i][1], f[i][2], f[i][3]);
    }

    float as[4], ad[4];
#pragma unroll
    for (int j = 0; j < 4; j++) { as[j] = att_s[tx * 4 + j]; ad[j] = att_d[tx * 4 + j]; }

#pragma unroll
    for (int i = 0; i < 4; i++) {
        int gr = row0 + ty * 4 + i;
        if (gr < N)
            *(float4*)&g_h[(long long)gr * OUT_DIM + tx * 4] =
                make_float4(f[i][0], f[i][1], f[i][2], f[i][3]);
        float ps = f[i][0] * as[0] + f[i][1] * as[1] + f[i][2] * as[2] + f[i][3] * as[3];
        float pd = f[i][0] * ad[0] + f[i][1] * ad[1] + f[i][2] * ad[2] + f[i][3] * ad[3];
#pragma unroll
        for (int o = 8; o >= 1; o >>= 1) {
            ps += __shfl_xor_sync(0xffffffffu, ps, o);
            pd += __shfl_xor_sync(0xffffffffu, pd, o);
        }
        if (tx == 0 && gr < N) { g_asrc[gr] = ps; g_adst[gr] = pd; }
    }
}

// ---------- K2: segment max over destinations (edges + self loops) ----------
// edge_index is INT32 (JAX default x64-disabled downcasts int64 -> int32).
__global__ __launch_bounds__(256)
void k_edge_max(const int* __restrict__ ei, int E, int N) {
    long long idx = (long long)blockIdx.x * blockDim.x + threadIdx.x;
    long long ET = (long long)E + N;
    if (idx >= ET) return;
    int s, d;
    if (idx < E) { s = clampi(ei[idx], N); d = clampi(ei[E + idx], N); }
    else         { s = d = (int)(idx - E); }
    float v = lrelu(g_asrc[s] + g_adst[d]);
    atomicMaxF(&g_emax[d], v);
}

// ---------- K3: w = exp(e - emax[dst]); denom[dst] += w; out[dst] += w*h[src] ----------
// 16 threads per edge; each thread covers 4 output dims via red.v4.f32.
__global__ __launch_bounds__(256)
void k_edge_scatter(const int* __restrict__ ei, int E, int N,
                    float* __restrict__ out) {
    long long gid = (long long)blockIdx.x * blockDim.x + threadIdx.x;
    long long e = gid >> 4;
    int t = (int)(gid & 15);
    long long ET = (long long)E + N;
    if (e >= ET) return;
    int s, d;
    if (e < E) { s = clampi(ei[e], N); d = clampi(ei[E + e], N); }
    else       { s = d = (int)(e - E); }
    float v = lrelu(g_asrc[s] + g_adst[d]);
    float w = __expf(v - g_emax[d]);
    if (t == 0) atomicAdd(&g_denom[d], w);
    float4 hv = *(const float4*)&g_h[(long long)s * OUT_DIM + t * 4];
    red_add4(out + (long long)d * OUT_DIM + t * 4, w * hv.x, w * hv.y, w * hv.z, w * hv.w);
}

// ---------- K4: out = (acc/denom + bias), then row-wise L2 normalize ----------
__global__ __launch_bounds__(256)
void k_finalize(float* __restrict__ out, const float* __restrict__ bias, int N) {
    int gid = blockIdx.x * blockDim.x + threadIdx.x;
    int row = gid >> 5;
    int lane = gid & 31;
    if (row >= N) return;
    float inv = 1.f / g_denom[row];
    float o0 = out[(long long)row * OUT_DIM + lane]      * inv + bias[lane];
    float o1 = out[(long long)row * OUT_DIM + 32 + lane] * inv + bias[32 + lane];
    float ss = o0 * o0 + o1 * o1;
#pragma unroll
    for (int o = 16; o >= 1; o >>= 1) ss += __shfl_xor_sync(0xffffffffu, ss, o);
    float nrm = sqrtf(ss);
    float sc = 1.f / fmaxf(nrm, 1e-12f);
    out[(long long)row * OUT_DIM + lane]      = o0 * sc;
    out[(long long)row * OUT_DIM + 32 + lane] = o1 * sc;
}

static inline int grid1(long long work, int block) {
    long long g = (work + block - 1) / block;
    return (int)(g < 1 ? 1 : g);
}

extern "C" void kernel_launch(void* const* d_in, const int* in_sizes, int n_in,
                              void* d_out, int out_size) {
    const float* x     = (const float*)d_in[0];
    const int*   ei    = (const int*)d_in[1];     // int32! (JAX x64 disabled)
    const float* W     = (const float*)d_in[2];
    const float* att_s = (const float*)d_in[3];
    const float* att_d = (const float*)d_in[4];
    const float* bias  = (const float*)d_in[5];
    float* out = (float*)d_out;

    int       N  = in_sizes[0] / IN_DIM;
    int       E  = in_sizes[1] / 2;
    long long ET = (long long)E + N;

    // K0: init
    k_init<<<grid1((long long)N * OUT_DIM, 256), 256>>>(out, N * OUT_DIM, N);
    // K1: GEMM + attention scores
    k_gemm<<<grid1(N, TM), 256>>>(x, W, att_s, att_d, N);
    // K2: segment max
    k_edge_max<<<grid1(ET, 256), 256>>>(ei, E, N);
    // K3: exp + denom + weighted scatter
    k_edge_scatter<<<grid1(ET * 16, 256), 256>>>(ei, E, N, out);
    // K4: finalize (divide, bias, L2 normalize)
    k_finalize<<<grid1((long long)N * 32, 256), 256>>>(out, bias, N);
}

// round 10
// speedup vs baseline: 1.0073x; 1.0031x over previous
#include <cuda_runtime.h>

typedef unsigned long long ull;

// Fixed problem shape: N=100000, IN=256, OUT=64, E=1600000 (guarded by in_sizes).
#define NMAX 100000
#define IN_DIM 256
#define OUT_DIM 64

__device__ __align__(16) float g_h[(size_t)NMAX * OUT_DIM];
__device__ float g_asrc[NMAX];
__device__ float g_adst[NMAX];
__device__ float g_emax[NMAX];
__device__ float g_denom[NMAX];

// ---------- packed f32x2 helpers (Blackwell) ----------
__device__ __forceinline__ ull packdup(float v) {
    ull r; asm("mov.b64 %0, {%1, %1};" : "=l"(r) : "f"(v)); return r;
}
__device__ __forceinline__ void fma2(ull& d, ull a, ull b) {
    asm("fma.rn.f32x2 %0, %1, %2, %0;" : "+l"(d) : "l"(a), "l"(b));
}
__device__ __forceinline__ void unpack2(ull v, float& a, float& b) {
    asm("mov.b64 {%0, %1}, %2;" : "=f"(a), "=f"(b) : "l"(v));
}

// vector reduction-add to global (sm_90+), 16B per op
__device__ __forceinline__ void red_add4(float* p, float a, float b, float c, float d) {
    asm volatile("red.global.add.v4.f32 [%0], {%1, %2, %3, %4};"
                 :: "l"(p), "f"(a), "f"(b), "f"(c), "f"(d) : "memory");
}

// float atomic max via int/uint ordering trick (init must be -inf)
__device__ __forceinline__ void atomicMaxF(float* addr, float val) {
    if (val >= 0.f) atomicMax((int*)addr, __float_as_int(val));
    else            atomicMin((unsigned int*)addr, __float_as_uint(val));
}

__device__ __forceinline__ float lrelu(float v) {
    return fmaxf(v, 0.f) + 0.2f * fminf(v, 0.f);
}

__device__ __forceinline__ int clampi(int v, int hi) {   // [0, hi)
    return min(max(v, 0), hi - 1);
}

// ---------- K0: init out=0, denom=0, emax=-inf ----------
__global__ void k_init(float* __restrict__ out, int n_out, int N) {
    int i = blockIdx.x * blockDim.x + threadIdx.x;
    if (i < n_out) out[i] = 0.f;
    if (i < N) { g_denom[i] = 0.f; g_emax[i] = __int_as_float(0xff800000); }
}

// ---------- K1: h = x @ W, a_src = h@att_src, a_dst = h@att_dst ----------
// 64x64 output tile per block, 256 threads (16x16), 4x4 register tile,
// inner product via packed fma.rn.f32x2 (2 cols per op).
#define TM 64
#define TK 32
__global__ __launch_bounds__(256)
void k_gemm(const float* __restrict__ x, const float* __restrict__ W,
            const float* __restrict__ att_s, const float* __restrict__ att_d, int N) {
    __shared__ float xs[TM][TK + 1];   // [m][k], stride 33: conflict-free scalar STS + broadcast LDS
    __shared__ float ws[TK][OUT_DIM];  // [k][n], natural row-major

    const int tid = threadIdx.x;
    const int tx = tid & 15;          // col group (4 cols)
    const int ty = tid >> 4;          // row group (4 rows)
    const int row0 = blockIdx.x * TM;

    ull acc[4][2];
#pragma unroll
    for (int i = 0; i < 4; i++) { acc[i][0] = 0ull; acc[i][1] = 0ull; }

    for (int kc = 0; kc < IN_DIM; kc += TK) {
        // load x tile: 64 rows x 32 k = 512 float4
#pragma unroll
        for (int it = 0; it < 2; ++it) {
            int idx = tid + it * 256;          // 0..511
            int m   = idx >> 3;                // row in tile
            int kq  = idx & 7;                 // float4 within k-chunk
            int gr  = row0 + m;
            float4 v = make_float4(0.f, 0.f, 0.f, 0.f);
            if (gr < N) v = *(const float4*)(x + (long long)gr * IN_DIM + kc + kq * 4);
            xs[m][kq * 4 + 0] = v.x; xs[m][kq * 4 + 1] = v.y;
            xs[m][kq * 4 + 2] = v.z; xs[m][kq * 4 + 3] = v.w;
        }
        // load W tile: 32 k x 64 n = 512 float4
#pragma unroll
        for (int it = 0; it < 2; ++it) {
            int idx = tid + it * 256;
            int k   = idx >> 4;
            int nq  = idx & 15;
            *(float4*)&ws[k][nq * 4] =
                *(const float4*)(W + (long long)(kc + k) * OUT_DIM + nq * 4);
        }
        __syncthreads();

#pragma unroll
        for (int k = 0; k < TK; ++k) {
            ulonglong2 bv = *(const ulonglong2*)&ws[k][tx * 4];  // (n0,n1),(n2,n3) packed
            float a0 = xs[ty * 4 + 0][k];
            float a1 = xs[ty * 4 + 1][k];
            float a2 = xs[ty * 4 + 2][k];
            float a3 = xs[ty * 4 + 3][k];
            ull A;
            A = packdup(a0); fma2(acc[0][0], A, bv.x); fma2(acc[0][1], A, bv.y);
            A = packdup(a1); fma2(acc[1][0], A, bv.x); fma2(acc[1][1], A, bv.y);
            A = packdup(a2); fma2(acc[2][0], A, bv.x); fma2(acc[2][1], A, bv.y);
            A = packdup(a3); fma2(acc[3][0], A, bv.x); fma2(acc[3][1], A, bv.y);
        }
        __syncthreads();
    }

    // unpack 4x4 tile
    float f[4][4];
#pragma unroll
    for (int i = 0; i < 4; i++) {
        unpack2(acc[i][0], f[i][0], f[i][1]);
        unpack2(acc[i][1], f[i][2], f[i][3]);
    }

    float as[4], ad[4];
#pragma unroll
    for (int j = 0; j < 4; j++) { as[j] = att_s[tx * 4 + j]; ad[j] = att_d[tx * 4 + j]; }

#pragma unroll
    for (int i = 0; i < 4; i++) {
        int gr = row0 + ty * 4 + i;
        if (gr < N)
            *(float4*)&g_h[(long long)gr * OUT_DIM + tx * 4] =
                make_float4(f[i][0], f[i][1], f[i][2], f[i][3]);
        float ps = f[i][0] * as[0] + f[i][1] * as[1] + f[i][2] * as[2] + f[i][3] * as[3];
        float pd = f[i][0] * ad[0] + f[i][1] * ad[1] + f[i][2] * ad[2] + f[i][3] * ad[3];
#pragma unroll
        for (int o = 8; o >= 1; o >>= 1) {
            ps += __shfl_xor_sync(0xffffffffu, ps, o);
            pd += __shfl_xor_sync(0xffffffffu, pd, o);
        }
        if (tx == 0 && gr < N) { g_asrc[gr] = ps; g_adst[gr] = pd; }
    }
}

// ---------- K2: segment max over destinations (edges + self loops) ----------
// edge_index is INT32 (JAX default x64-disabled downcasts int64 -> int32).
__global__ __launch_bounds__(256)
void k_edge_max(const int* __restrict__ ei, int E, int N) {
    long long idx = (long long)blockIdx.x * blockDim.x + threadIdx.x;
    long long ET = (long long)E + N;
    if (idx >= ET) return;
    int s, d;
    if (idx < E) { s = clampi(ei[idx], N); d = clampi(ei[E + idx], N); }
    else         { s = d = (int)(idx - E); }
    float v = lrelu(g_asrc[s] + g_adst[d]);
    atomicMaxF(&g_emax[d], v);
}

// ---------- K3: w = exp(e - emax[dst]); denom[dst] += w; out[dst] += w*h[src] ----------
// 16 threads per edge; each thread covers 4 output dims via red.v4.f32.
__global__ __launch_bounds__(256)
void k_edge_scatter(const int* __restrict__ ei, int E, int N,
                    float* __restrict__ out) {
    long long gid = (long long)blockIdx.x * blockDim.x + threadIdx.x;
    long long e = gid >> 4;
    int t = (int)(gid & 15);
    long long ET = (long long)E + N;
    if (e >= ET) return;
    int s, d;
    if (e < E) { s = clampi(ei[e], N); d = clampi(ei[E + e], N); }
    else       { s = d = (int)(e - E); }
    float v = lrelu(g_asrc[s] + g_adst[d]);
    float w = __expf(v - g_emax[d]);
    if (t == 0) atomicAdd(&g_denom[d], w);
    float4 hv = *(const float4*)&g_h[(long long)s * OUT_DIM + t * 4];
    red_add4(out + (long long)d * OUT_DIM + t * 4, w * hv.x, w * hv.y, w * hv.z, w * hv.w);
}

// ---------- K4: out = (acc/denom + bias), then row-wise L2 normalize ----------
__global__ __launch_bounds__(256)
void k_finalize(float* __restrict__ out, const float* __restrict__ bias, int N) {
    int gid = blockIdx.x * blockDim.x + threadIdx.x;
    int row = gid >> 5;
    int lane = gid & 31;
    if (row >= N) return;
    float inv = 1.f / g_denom[row];
    float o0 = out[(long long)row * OUT_DIM + lane]      * inv + bias[lane];
    float o1 = out[(long long)row * OUT_DIM + 32 + lane] * inv + bias[32 + lane];
    float ss = o0 * o0 + o1 * o1;
#pragma unroll
    for (int o = 16; o >= 1; o >>= 1) ss += __shfl_xor_sync(0xffffffffu, ss, o);
    float nrm = sqrtf(ss);
    float sc = 1.f / fmaxf(nrm, 1e-12f);
    out[(long long)row * OUT_DIM + lane]      = o0 * sc;
    out[(long long)row * OUT_DIM + 32 + lane] = o1 * sc;
}

static inline int grid1(long long work, int block) {
    long long g = (work + block - 1) / block;
    return (int)(g < 1 ? 1 : g);
}

extern "C" void kernel_launch(void* const* d_in, const int* in_sizes, int n_in,
                              void* d_out, int out_size) {
    const float* x     = (const float*)d_in[0];
    const int*   ei    = (const int*)d_in[1];     // int32! (JAX x64 disabled)
    const float* W     = (const float*)d_in[2];
    const float* att_s = (const float*)d_in[3];
    const float* att_d = (const float*)d_in[4];
    const float* bias  = (const float*)d_in[5];
    float* out = (float*)d_out;

    int       N  = in_sizes[0] / IN_DIM;
    int       E  = in_sizes[1] / 2;
    long long ET = (long long)E + N;

    // K0: init
    k_init<<<grid1((long long)N * OUT_DIM, 256), 256>>>(out, N * OUT_DIM, N);
    // K1: GEMM + attention scores
    k_gemm<<<grid1(N, TM), 256>>>(x, W, att_s, att_d, N);
    // K2: segment max
    k_edge_max<<<grid1(ET, 256), 256>>>(ei, E, N);
    // K3: exp + denom + weighted scatter
    k_edge_scatter<<<grid1(ET * 16, 256), 256>>>(ei, E, N, out);
    // K4: finalize (divide, bias, L2 normalize)
    k_finalize<<<grid1((long long)N * 32, 256), 256>>>(out, bias, N);
}